// round 17
// baseline (speedup 1.0000x reference)
#include <cuda_runtime.h>
#include <cuda_fp16.h>
#include <cstdint>

// AWD-LSTM persistent kernel v10: v9 + per-half (64-block) barriers (batch
// halves are provably independent), fp16 xi, HADD2 gate tree, front-loaded
// A LDGs. T=1024, B=64, DIN=512, H=1024.
// Inputs: x[T,B,DIN], h0[B,H], c0[B,H], Wi[4H,DIN], bi[4H], Wh[4H,H], bh[4H],
//         input_tokens[T,B] i32.  Output: [ out(T*B*H) | hT(B*H) | cT(B*H) ].

#define TT 1024
#define BB 64
#define DD 512
#define HH 1024
#define GG 4096
#define GRID 128
#define BH   (BB * HH)
#define TBH  ((size_t)TT * BB * HH)
#define PSTR 36                 // Ps row stride (4B words)
#define PSLICE (32 * PSTR)      // words per slice array

// g_h: fp16, A-fragment layout for m16n8k16 (v4b mapping).
__device__ unsigned g_xih[(size_t)TT * BB * GG / 2];  // 537 MB, half2 col-pairs
__device__ unsigned g_h[2][4 * 64 * 128];             // 2 x 128 KB
__device__ __align__(128) unsigned g_cnt2[64];        // [0]=half0, [32]=half1
__device__ __align__(128) unsigned g_epoch2[64];

__device__ __forceinline__ unsigned f2h2(float x, float y) {
    unsigned r;
    asm("cvt.rn.f16x2.f32 %0, %1, %2;" : "=r"(r) : "f"(y), "f"(x));
    return r;
}

__device__ __forceinline__ float2 h22f2(unsigned u) {
    __half2 h = *(__half2*)&u;
    return __half22float2(h);
}

__device__ __forceinline__ unsigned hadd2u(unsigned a, unsigned b) {
    __half2 r = __hadd2(*(__half2*)&a, *(__half2*)&b);
    return *(unsigned*)&r;
}

// f32-accumulate (xi GEMM)
__device__ __forceinline__ void mma_f16(float d[4], const unsigned a[4], const unsigned b[2]) {
    asm volatile(
        "mma.sync.aligned.m16n8k16.row.col.f32.f16.f16.f32 "
        "{%0,%1,%2,%3}, {%4,%5,%6,%7}, {%8,%9}, {%0,%1,%2,%3};\n"
        : "+f"(d[0]), "+f"(d[1]), "+f"(d[2]), "+f"(d[3])
        : "r"(a[0]), "r"(a[1]), "r"(a[2]), "r"(a[3]), "r"(b[0]), "r"(b[1]));
}

// f16-accumulate (recurrent GEMM)
__device__ __forceinline__ void mma_f16h(unsigned d[2], const unsigned a[4], const unsigned b[2]) {
    asm volatile(
        "mma.sync.aligned.m16n8k16.row.col.f16.f16.f16.f16 "
        "{%0,%1}, {%2,%3,%4,%5}, {%6,%7}, {%0,%1};\n"
        : "+r"(d[0]), "+r"(d[1])
        : "r"(a[0]), "r"(a[1]), "r"(a[2]), "r"(a[3]), "r"(b[0]), "r"(b[1]));
}

__device__ __forceinline__ float sigmf(float x) {
    return __fdividef(1.f, 1.f + __expf(-x));
}
__device__ __forceinline__ float tanhx(float x) {
    return 2.f * sigmf(2.f * x) - 1.f;
}

// ---------------------------------------------------------------------------
// init: g_h[0] = fp16(h0) in fragment layout; reset both barrier pairs.
// ---------------------------------------------------------------------------
__global__ void init_kernel(const float* __restrict__ h0) {
    int w = blockIdx.x * 256 + threadIdx.x;        // word index, 32768 total
    if (w < 4 * 64 * 128) {
        int mb = w >> 13, u = (w >> 7) & 63;
        int lane = (w >> 2) & 31, frag = w & 3;
        int r = ((frag & 1) << 3) | (lane >> 2);
        int kin = ((frag >> 1) << 3) | ((lane & 3) << 1);
        int b = mb * 16 + r, col = u * 16 + kin;
        float2 v = *(const float2*)(h0 + (size_t)b * HH + col);
        g_h[0][w] = f2h2(v.x, v.y);
    }
    if (blockIdx.x == 0 && threadIdx.x < 2) {
        g_cnt2[threadIdx.x * 32] = 0;
        g_epoch2[threadIdx.x * 32] = 0;
    }
}

// ---------------------------------------------------------------------------
// xi = x @ Wi^T + bi, fp16 m16n8k16 (f32 acc), fp16 output. M=65536, K=512.
// ---------------------------------------------------------------------------
__global__ __launch_bounds__(256) void xi_gemm(const float* __restrict__ x,
                                               const float* __restrict__ Wi,
                                               const float* __restrict__ bi) {
    __shared__ __align__(16) unsigned As2[64][20];   // half2, stride 20
    __shared__ __align__(16) unsigned Bs2[64][20];
    const int n0 = blockIdx.x * 64;
    const int m0 = blockIdx.y * 64;
    const int tid = threadIdx.x;
    const int lane = tid & 31, wid = tid >> 5;
    const int wm = wid >> 2, wn = wid & 3;
    const int g = lane >> 2, tg = lane & 3;

    float acc[2][2][4] = {};

    for (int k0 = 0; k0 < DD; k0 += 32) {
#pragma unroll
        for (int i = 0; i < 2; i++) {
            int f = tid + i * 256;
            int r = f >> 3, kq = (f & 7) << 2, k2 = (f & 7) << 1;
            float4 v = *(const float4*)(x + (size_t)(m0 + r) * DD + k0 + kq);
            As2[r][k2] = f2h2(v.x, v.y);
            As2[r][k2 + 1] = f2h2(v.z, v.w);
            float4 w = *(const float4*)(Wi + (size_t)(n0 + r) * DD + k0 + kq);
            Bs2[r][k2] = f2h2(w.x, w.y);
            Bs2[r][k2 + 1] = f2h2(w.z, w.w);
        }
        __syncthreads();

#pragma unroll
        for (int kk2 = 0; kk2 < 16; kk2 += 8) {
            unsigned a[2][4], bf[2][2];
#pragma unroll
            for (int mi = 0; mi < 2; mi++) {
                int r = wm * 32 + mi * 16;
                a[mi][0] = As2[r + g][kk2 + tg];
                a[mi][1] = As2[r + g + 8][kk2 + tg];
                a[mi][2] = As2[r + g][kk2 + tg + 4];
                a[mi][3] = As2[r + g + 8][kk2 + tg + 4];
            }
#pragma unroll
            for (int ni = 0; ni < 2; ni++) {
                int c = wn * 16 + ni * 8;
                bf[ni][0] = Bs2[c + g][kk2 + tg];
                bf[ni][1] = Bs2[c + g][kk2 + tg + 4];
            }
#pragma unroll
            for (int mi = 0; mi < 2; mi++)
#pragma unroll
                for (int ni = 0; ni < 2; ni++)
                    mma_f16(acc[mi][ni], a[mi], bf[ni]);
        }
        __syncthreads();
    }

#pragma unroll
    for (int mi = 0; mi < 2; mi++)
#pragma unroll
        for (int ni = 0; ni < 2; ni++) {
            int row = m0 + wm * 32 + mi * 16 + g;
            int col = n0 + wn * 16 + ni * 8 + 2 * tg;   // even
            float2 bv = *(const float2*)(bi + col);
            g_xih[((size_t)row * GG + col) >> 1] =
                f2h2(acc[mi][ni][0] + bv.x, acc[mi][ni][1] + bv.y);
            g_xih[((size_t)(row + 8) * GG + col) >> 1] =
                f2h2(acc[mi][ni][2] + bv.x, acc[mi][ni][3] + bv.y);
        }
}

// ---------------------------------------------------------------------------
// Persistent recurrence, M-split + per-half barriers. grid=128 = mh(2) x
// cg(64); block 512 thr = 16 k-slice warps (K=64 each).
// The two batch halves are fully independent (LSTM is per-batch-row); each
// half runs its own 64-block barrier on its own cache lines.
// ---------------------------------------------------------------------------
__global__ __launch_bounds__(512, 1) void lstm_persist(
    const float* __restrict__ Wh, const float* __restrict__ bh,
    const int* __restrict__ tok, const float* __restrict__ c0,
    float* __restrict__ out, int ne)
{
    extern __shared__ __align__(16) unsigned smem_dyn[];
    unsigned* Bsf = smem_dyn;                        // 32768 words = 128 KB
    unsigned* Psf = smem_dyn + 32768;                // 16*PSLICE words = 72 KB

    const int bid = blockIdx.x;
    const int mh = bid >> 6;                         // batch half (0..1)
    const int cg = bid & 63;                         // column group (0..63)
    const int tid = threadIdx.x, lane = tid & 31, wid = tid >> 5;
    const int ks = wid;                              // k-slice (0..15)
    const int g = lane >> 2, tg = lane & 3;

    unsigned* mycnt = &g_cnt2[mh * 32];
    unsigned* myepoch = &g_epoch2[mh * 32];

    // One-time: Wh -> fp16 fragment-ready smem (N=64 tile), v9 mapping.
#pragma unroll
    for (int i = 0; i < 64; i++) {
        int idx = tid + i * 512;                     // 0..32767
        int u = idx >> 9, rest = idx & 511;
        int ntp = rest >> 7, rr = rest & 127;
        int ln = rr >> 2, q = rr & 3;
        int nt = ntp * 2 + (q >> 1), breg = q & 1;
        int n = nt * 8 + (ln >> 2);
        int grow = (n >> 4) * HH + cg * 16 + (n & 15);
        int k = u * 16 + 2 * (ln & 3) + 8 * breg;
        float2 v = *(const float2*)(Wh + (size_t)grow * HH + k);
        Bsf[idx] = f2h2(v.x, v.y);
    }

    // Gate-phase mapping (threads 0..255): 2 adjacent cols per thread.
    const bool gateth = (wid < 8);
    const int bq = (lane >> 2) + 8 * (wid >> 1);     // local row 0..31
    const int jp = (lane & 3) + 4 * (wid & 1);       // col pair 0..7
    const int b = mh * 32 + bq;                      // global batch row
    const int colE = cg * 16 + 2 * jp;               // even global column
    float2 bhv[4], creg = make_float2(0.f, 0.f), hreg = make_float2(0.f, 0.f);
    unsigned hoff = 0;
    if (gateth) {
#pragma unroll
        for (int gate = 0; gate < 4; gate++)
            bhv[gate] = *(const float2*)(bh + gate * HH + colE);
        creg = *(const float2*)(c0 + (size_t)b * HH + colE);
        int mb = b >> 4, r = b & 15;
        int ln2 = (r & 7) * 4 + (jp & 3);
        int frag = ((jp >> 2) << 1) | (r >> 3);
        hoff = ((unsigned)(mb << 6 | cg) << 7) + ln2 * 4 + frag;
    }
    __syncthreads();

    // Loop-carried xi prefetch for step 0 (one half2 word per gate).
    float2 xr[4];
    if (gateth) {
        const unsigned* xb = g_xih + (((size_t)b * GG) + colE) / 2;
#pragma unroll
        for (int gate = 0; gate < 4; gate++)
            xr[gate] = h22f2(__ldcg(xb + gate * (HH / 2)));
    }

    for (int t = 0; t < TT; t++) {
        // GEMM: preact[32x64] = h[t-1] @ WhTile^T, K-slice ks (K=64).
        const uint4* ab = (const uint4*)g_h[t & 1];
        // Front-load all 8 A tiles (max MLP through the post-release burst).
        uint4 Ar[2][4];
#pragma unroll
        for (int kk = 0; kk < 4; kk++) {
            int u = 4 * ks + kk;
            Ar[0][kk] = __ldcg(ab + ((2 * mh + 0) * 64 + u) * 32 + lane);
            Ar[1][kk] = __ldcg(ab + ((2 * mh + 1) * 64 + u) * 32 + lane);
        }
        unsigned acch[2][8][2] = {};
#pragma unroll
        for (int kk = 0; kk < 4; kk++) {
            int u = 4 * ks + kk;
            const uint4* bp = (const uint4*)Bsf + (u * 4) * 32 + lane;
            uint4 B0 = bp[0];
            uint4 B1 = bp[32];
            uint4 B2 = bp[64];
            uint4 B3 = bp[96];
            unsigned af0[4] = { Ar[0][kk].x, Ar[0][kk].y, Ar[0][kk].z, Ar[0][kk].w };
            unsigned af1[4] = { Ar[1][kk].x, Ar[1][kk].y, Ar[1][kk].z, Ar[1][kk].w };
            unsigned bf[8][2] = {
                { B0.x, B0.y }, { B0.z, B0.w }, { B1.x, B1.y }, { B1.z, B1.w },
                { B2.x, B2.y }, { B2.z, B2.w }, { B3.x, B3.y }, { B3.z, B3.w } };
#pragma unroll
            for (int nt = 0; nt < 8; nt++) {
                mma_f16h(acch[0][nt], af0, bf[nt]);
                mma_f16h(acch[1][nt], af1, bf[nt]);
            }
        }

        // Single-phase reduction: slice ks owns Psf[ks]; raw f16x2 partials.
        {
            unsigned* P = Psf + ks * PSLICE;
#pragma unroll
            for (int mbi = 0; mbi < 2; mbi++)
#pragma unroll
                for (int nt = 0; nt < 8; nt++) {
                    int c2 = nt * 4 + tg;
                    P[(mbi * 16 + g) * PSTR + c2]     = acch[mbi][nt][0];
                    P[(mbi * 16 + g + 8) * PSTR + c2] = acch[mbi][nt][1];
                }
        }
        __syncthreads();

        // Gate phase: threads 0..255, 2 cols each; HADD2 pair tree.
        if (gateth) {
            float kc = (t >= 2 && __ldg(tok + (t - 1) * BB + b) == 0) ? 0.f : 1.f;
            float2 pre[4];
#pragma unroll
            for (int gate = 0; gate < 4; gate++) {
                int c2 = gate * 8 + jp;
                const unsigned* P = Psf + bq * PSTR + c2;
                float2 s = make_float2(0.f, 0.f);
#pragma unroll
                for (int sl = 0; sl < 8; sl++) {
                    float2 v = h22f2(hadd2u(P[(2 * sl) * PSLICE],
                                            P[(2 * sl + 1) * PSLICE]));
                    s.x += v.x; s.y += v.y;
                }
                pre[gate] = make_float2(s.x + xr[gate].x + bhv[gate].x,
                                        s.y + xr[gate].y + bhv[gate].y);
            }
            float h2[2], c2v[2];
#pragma unroll
            for (int z = 0; z < 2; z++) {
                float pi = z ? pre[0].y : pre[0].x;
                float pf = z ? pre[1].y : pre[1].x;
                float po = z ? pre[2].y : pre[2].x;
                float pg = z ? pre[3].y : pre[3].x;
                float iv = sigmf(pi);
                float fv = sigmf(pf);
                float ov = sigmf(po);
                float gv = tanhx(pg);
                float cold = (z ? creg.y : creg.x) * kc;
                float cn = fv * cold + iv * gv;
                c2v[z] = cn;
                h2[z] = ov * tanhx(cn);
            }
            creg = make_float2(c2v[0], c2v[1]);
            hreg = make_float2(h2[0], h2[1]);
            float kn = ((t + 1) >= 2 && __ldg(tok + t * BB + b) == 0) ? 0.f : 1.f;
            g_h[(t + 1) & 1][hoff] = f2h2(h2[0] * kn, h2[1] * kn);
        }

        // Per-half barrier arrival immediately after g_h stores.
        __syncthreads();
        if (tid == 0) {
            __threadfence();
            unsigned old = atomicAdd(mycnt, 1u);
            if (old == (unsigned)(t + 1) * 64u - 1u) {
                __threadfence();
                atomicExch(myepoch, (unsigned)(t + 1));
            }
        }

        // Off-critical-path work while the barrier settles.
        if (gateth) {
            *(float2*)(out + (size_t)t * BH + (size_t)b * HH + colE) = hreg;
            if (t + 1 < TT) {
                const unsigned* xb =
                    g_xih + (((size_t)(t + 1) * BB + b) * GG + colE) / 2;
#pragma unroll
                for (int gate = 0; gate < 4; gate++)
                    xr[gate] = h22f2(__ldcg(xb + gate * (HH / 2)));
            }
        }

        if (tid == 0) {
            unsigned e;
            do {
                asm volatile("ld.global.relaxed.gpu.b32 %0, [%1];"
                             : "=r"(e) : "l"(myepoch));
            } while (e < (unsigned)(t + 1));
            __threadfence();
        }
        __syncthreads();
    }

    // hT / cT tail from registers.
    if (gateth) {
        size_t off = (size_t)b * HH + colE;
        if (ne >= 1) *(float2*)(out + TBH + off) = hreg;
        if (ne >= 2) *(float2*)(out + TBH + BH + off) = creg;
    }
}

extern "C" void kernel_launch(void* const* d_in, const int* in_sizes, int n_in,
                              void* d_out, int out_size) {
    const float* x  = (const float*)d_in[0];
    const float* h0 = (const float*)d_in[1];
    const float* c0 = (const float*)d_in[2];
    const float* Wi = (const float*)d_in[3];
    const float* bi = (const float*)d_in[4];
    const float* Wh = (const float*)d_in[5];
    const float* bh = (const float*)d_in[6];
    const int* tok  = (const int*)d_in[7];
    float* out = (float*)d_out;

    const int dyn_smem = (32768 + 16 * PSLICE) * 4;  // 128 KB + 72 KB
    cudaFuncSetAttribute(lstm_persist, cudaFuncAttributeMaxDynamicSharedMemorySize, dyn_smem);

    init_kernel<<<(4 * 64 * 128 + 255) / 256, 256>>>(h0);
    xi_gemm<<<dim3(GG / 64, (TT * BB) / 64), 256>>>(x, Wi, bi);

    long long extra = ((long long)out_size - (long long)TBH) / BH;
    int ne = extra < 0 ? 0 : (extra > 2 ? 2 : (int)extra);

    lstm_persist<<<GRID, 512, dyn_smem>>>(Wh, bh, tok, c0, out, ne);
}